// round 7
// baseline (speedup 1.0000x reference)
#include <cuda_runtime.h>
#include <cuda_bf16.h>
#include <cstdint>
#include <math.h>

#define N_NODES 50000
#define N_EDGES 500000
#define EN      (N_EDGES + N_NODES)   // 550000 incl. self loops
#define D_IN    128
#define D_HID   256
#define BM      128
#define BN      128
#define BK      64
#define N_CTAS  ((N_NODES + BM - 1) / BM)   // 391
#define M_PAD   (N_CTAS * BM)               // 50048

// ---------------- async-copy helpers (portable PTX, sm_80+) -----------------
__device__ __forceinline__ uint32_t smem_to_u32(const void* p) {
    uint32_t a;
    asm("{ .reg .u64 t; cvta.to.shared.u64 t, %1; cvt.u32.u64 %0, t; }" : "=r"(a) : "l"(p));
    return a;
}
__device__ __forceinline__ void cp_async16(uint32_t s, const void* g) {
    asm volatile("cp.async.cg.shared.global [%0], [%1], 16;" :: "r"(s), "l"(g));
}
__device__ __forceinline__ void cp_commit() {
    asm volatile("cp.async.commit_group;" ::: "memory");
}
template <int N>
__device__ __forceinline__ void cp_wait() {
    asm volatile("cp.async.wait_group %0;" :: "n"(N) : "memory");
}
__device__ __forceinline__ void ldsm_x4(uint32_t* r, uint32_t addr) {
    asm volatile("ldmatrix.sync.aligned.m8n8.x4.shared.b16 {%0,%1,%2,%3}, [%4];"
                 : "=r"(r[0]), "=r"(r[1]), "=r"(r[2]), "=r"(r[3]) : "r"(addr));
}
__device__ __forceinline__ void mma_bf16(float* c, const uint32_t* a, const uint32_t* b) {
    asm volatile(
        "mma.sync.aligned.m16n8k16.row.col.f32.bf16.bf16.f32 "
        "{%0,%1,%2,%3}, {%4,%5,%6,%7}, {%8,%9}, {%0,%1,%2,%3};"
        : "+f"(c[0]), "+f"(c[1]), "+f"(c[2]), "+f"(c[3])
        : "r"(a[0]), "r"(a[1]), "r"(a[2]), "r"(a[3]), "r"(b[0]), "r"(b[1]));
}

// ---------------- device scratch (static globals; no allocation) ------------
__device__ int   g_deg[N_NODES];          // zeroed at end of every replay by k_scan
__device__ int   g_row_ptr[N_NODES + 1];
__device__ int   g_pos[N_NODES];
__device__ int   g_col[EN];
__device__ float g_enorm[EN];
__device__ float g_dinv[N_NODES];
__device__ __align__(16) float g_h[(size_t)N_NODES * D_HID];           // fp32 activations
__device__ __align__(16) __nv_bfloat16 g_ah[(size_t)M_PAD * D_HID];    // split-hi of agg
__device__ __align__(16) __nv_bfloat16 g_al[(size_t)M_PAD * D_HID];    // split-lo of agg
__device__ __align__(16) __nv_bfloat16 g_w1h[D_HID * D_IN];            // W^T [256,128]
__device__ __align__(16) __nv_bfloat16 g_w1l[D_HID * D_IN];
__device__ __align__(16) __nv_bfloat16 g_w2h[D_HID * D_HID];           // W^T [256,256]
__device__ __align__(16) __nv_bfloat16 g_w2l[D_HID * D_HID];
__device__ __align__(16) __nv_bfloat16 g_w3h[D_HID * D_HID];
__device__ __align__(16) __nv_bfloat16 g_w3l[D_HID * D_HID];

// ---------------- CSR + weight split (fused launch 1) ------------------------
#define W1_ELEMS (D_IN * D_HID)
#define W23_ELEMS (D_HID * D_HID)
#define SPLIT_ELEMS (W1_ELEMS + 2 * W23_ELEMS)   // 163840

__device__ __forceinline__ void split_one(const float* W, int K, int idx,
                                          __nv_bfloat16* oh, __nv_bfloat16* ol) {
    int k = idx / D_HID, n = idx % D_HID;
    float v = W[idx];
    __nv_bfloat16 h = __float2bfloat16(v);
    oh[(size_t)n * K + k] = h;
    ol[(size_t)n * K + k] = __float2bfloat16(v - __bfloat162float(h));
}

__global__ void k_count_split(const int* __restrict__ ei,
                              const float* __restrict__ W1,
                              const float* __restrict__ W2,
                              const float* __restrict__ W3) {
    int idx = blockIdx.x * blockDim.x + threadIdx.x;
    if (idx < N_EDGES) {
        atomicAdd(&g_deg[ei[N_EDGES + idx]], 1);
        return;
    }
    int j = idx - N_EDGES;
    if (j < W1_ELEMS) {
        split_one(W1, D_IN, j, g_w1h, g_w1l);
    } else if (j < W1_ELEMS + W23_ELEMS) {
        split_one(W2, D_HID, j - W1_ELEMS, g_w2h, g_w2l);
    } else if (j < SPLIT_ELEMS) {
        split_one(W3, D_HID, j - W1_ELEMS - W23_ELEMS, g_w3h, g_w3l);
    }
}

// Single-block scan. Degree = g_deg[i] + 1 (self loop). Zeroes g_deg for the
// next graph replay (deterministic: every execution starts from zeroed g_deg).
__global__ void k_scan() {
    __shared__ int s[1024];
    const int t = threadIdx.x;
    const int CH = (N_NODES + 1023) / 1024;
    int start = t * CH;
    int end = start + CH; if (end > N_NODES) end = N_NODES;
    if (start > N_NODES) start = N_NODES;
    int sum = 0;
#pragma unroll 4
    for (int i = start; i < end; i++) sum += g_deg[i] + 1;
    s[t] = sum;
    __syncthreads();
    for (int off = 1; off < 1024; off <<= 1) {
        int v = (t >= off) ? s[t - off] : 0;
        __syncthreads();
        s[t] += v;
        __syncthreads();
    }
    int prefix = (t == 0) ? 0 : s[t - 1];
    for (int i = start; i < end; i++) {
        int d = g_deg[i] + 1;
        g_deg[i] = 0;                       // reset for next replay
        g_row_ptr[i] = prefix;
        g_pos[i] = prefix;
        g_dinv[i] = rsqrtf((float)d);
        prefix += d;
    }
    if (t == 0) g_row_ptr[N_NODES] = s[1023];
}

__global__ void k_fill(const int* __restrict__ ei) {
    int idx = blockIdx.x * blockDim.x + threadIdx.x;
    if (idx < N_EDGES) {
        int s = ei[idx];
        int d = ei[N_EDGES + idx];
        int p = atomicAdd(&g_pos[d], 1);
        g_col[p] = s;
        g_enorm[p] = g_dinv[s] * g_dinv[d];
    } else if (idx < EN) {
        int i = idx - N_EDGES;
        int p = atomicAdd(&g_pos[i], 1);
        g_col[p] = i;
        float di = g_dinv[i];
        g_enorm[p] = di * di;
    }
}

// ---------------- aggregation + fp32->bf16 hi/lo split ----------------------
__device__ __forceinline__ void split_store4(__nv_bfloat16* oh, __nv_bfloat16* ol,
                                             size_t off, float4 a) {
    __nv_bfloat16 hx = __float2bfloat16(a.x);
    __nv_bfloat16 hy = __float2bfloat16(a.y);
    __nv_bfloat16 hz = __float2bfloat16(a.z);
    __nv_bfloat16 hw = __float2bfloat16(a.w);
    union { __nv_bfloat162 b[2]; uint2 u; } H, L;
    H.b[0] = __halves2bfloat162(hx, hy);
    H.b[1] = __halves2bfloat162(hz, hw);
    L.b[0] = __halves2bfloat162(__float2bfloat16(a.x - __bfloat162float(hx)),
                                __float2bfloat16(a.y - __bfloat162float(hy)));
    L.b[1] = __halves2bfloat162(__float2bfloat16(a.z - __bfloat162float(hz)),
                                __float2bfloat16(a.w - __bfloat162float(hw)));
    *reinterpret_cast<uint2*>(oh + off) = H.u;
    *reinterpret_cast<uint2*>(ol + off) = L.u;
}

// 2-way edge unroll: two independent load->FMA chains per step (MLP x2).
template <int D>   // 128 or 256
__global__ __launch_bounds__(256) void k_agg_split(
        const float* __restrict__ feat,
        __nv_bfloat16* __restrict__ oh,
        __nv_bfloat16* __restrict__ ol) {
    const int warp = blockIdx.x * (blockDim.x >> 5) + (threadIdx.x >> 5);
    const int lane = threadIdx.x & 31;
    if (warp >= N_NODES) return;
    const int rs = g_row_ptr[warp];
    const int re = g_row_ptr[warp + 1];
    const float4* feat4 = reinterpret_cast<const float4*>(feat);

    float4 aA0 = make_float4(0.f, 0.f, 0.f, 0.f);
    float4 aA1 = make_float4(0.f, 0.f, 0.f, 0.f);
    float4 aB0 = make_float4(0.f, 0.f, 0.f, 0.f);
    float4 aB1 = make_float4(0.f, 0.f, 0.f, 0.f);

    for (int j = rs; j < re; j += 32) {
        int m = re - j; if (m > 32) m = 32;
        int c = 0; float w = 0.f;
        if (lane < m) { c = g_col[j + lane]; w = g_enorm[j + lane]; }
        int k = 0;
        for (; k + 1 < m; k += 2) {
            int   c0 = __shfl_sync(0xffffffffu, c, k);
            float w0 = __shfl_sync(0xffffffffu, w, k);
            int   c1 = __shfl_sync(0xffffffffu, c, k + 1);
            float w1 = __shfl_sync(0xffffffffu, w, k + 1);
            const float4* r0 = feat4 + (size_t)c0 * (D / 4);
            const float4* r1 = feat4 + (size_t)c1 * (D / 4);
            float4 v0 = __ldg(&r0[lane]);
            float4 v1 = __ldg(&r1[lane]);
            aA0.x = fmaf(w0, v0.x, aA0.x); aA0.y = fmaf(w0, v0.y, aA0.y);
            aA0.z = fmaf(w0, v0.z, aA0.z); aA0.w = fmaf(w0, v0.w, aA0.w);
            aB0.x = fmaf(w1, v1.x, aB0.x); aB0.y = fmaf(w1, v1.y, aB0.y);
            aB0.z = fmaf(w1, v1.z, aB0.z); aB0.w = fmaf(w1, v1.w, aB0.w);
            if (D == 256) {
                float4 u0 = __ldg(&r0[lane + 32]);
                float4 u1 = __ldg(&r1[lane + 32]);
                aA1.x = fmaf(w0, u0.x, aA1.x); aA1.y = fmaf(w0, u0.y, aA1.y);
                aA1.z = fmaf(w0, u0.z, aA1.z); aA1.w = fmaf(w0, u0.w, aA1.w);
                aB1.x = fmaf(w1, u1.x, aB1.x); aB1.y = fmaf(w1, u1.y, aB1.y);
                aB1.z = fmaf(w1, u1.z, aB1.z); aB1.w = fmaf(w1, u1.w, aB1.w);
            }
        }
        if (k < m) {
            int   c0 = __shfl_sync(0xffffffffu, c, k);
            float w0 = __shfl_sync(0xffffffffu, w, k);
            const float4* r0 = feat4 + (size_t)c0 * (D / 4);
            float4 v0 = __ldg(&r0[lane]);
            aA0.x = fmaf(w0, v0.x, aA0.x); aA0.y = fmaf(w0, v0.y, aA0.y);
            aA0.z = fmaf(w0, v0.z, aA0.z); aA0.w = fmaf(w0, v0.w, aA0.w);
            if (D == 256) {
                float4 u0 = __ldg(&r0[lane + 32]);
                aA1.x = fmaf(w0, u0.x, aA1.x); aA1.y = fmaf(w0, u0.y, aA1.y);
                aA1.z = fmaf(w0, u0.z, aA1.z); aA1.w = fmaf(w0, u0.w, aA1.w);
            }
        }
    }
    aA0.x += aB0.x; aA0.y += aB0.y; aA0.z += aB0.z; aA0.w += aB0.w;
    split_store4(oh, ol, (size_t)warp * D + lane * 4, aA0);
    if (D == 256) {
        aA1.x += aB1.x; aA1.y += aB1.y; aA1.z += aB1.z; aA1.w += aB1.w;
        split_store4(oh, ol, (size_t)warp * D + 128 + lane * 4, aA1);
    }
}

// ---------------- split-bf16 mma.sync GEMM, single K-pass -------------------
// C = Ah@Bh^T + Ah@Bl^T + Al@Bh^T + bias. B (hi+lo, full K) is SMEM-resident,
// loaded once; A (hi+lo) streamed double-buffered in BK=64 chunks. All three
// terms accumulate into one acc per chunk with shared fragments.
// SMEM: A stages 2 x 32 KB @0, B at 64 KB: Bh chunks then Bl chunks (16 KB ea).
#define A_STAGE 32768
#define B_BASE  65536
#define SMEM_DYN_FOR(KP) (B_BASE + 2 * (KP / BK) * 16384)

template <int KP, bool RELU>
__global__ __launch_bounds__(256, 1) void k_gemm_mma(
    const __nv_bfloat16* __restrict__ Ah, const __nv_bfloat16* __restrict__ Al,
    const __nv_bfloat16* __restrict__ Bh, const __nv_bfloat16* __restrict__ Bl,
    const float* __restrict__ bias, float* __restrict__ C) {
    extern __shared__ __align__(128) char smem[];
    const uint32_t sb = smem_to_u32(smem);
    const int tid  = threadIdx.x;
    const int wid  = tid >> 5;
    const int lane = tid & 31;
    const int wm   = wid >> 1;           // 0..3  (M)
    const int wn   = wid & 1;            // 0..1  (N)
    const int m0   = blockIdx.y * BM;
    const int n0   = blockIdx.x * BN;
    constexpr int TP = KP / BK;          // K chunks (2 or 4)

    // ---- load ALL of B (hi+lo) once: per k-chunk tiles of 128 rows x 128 B
#pragma unroll
    for (int i = 0; i < TP * 4; ++i) {
        int cc = tid + i * 256;              // 0 .. TP*1024-1
        int kchunk = cc >> 10;
        int r  = (cc >> 3) & 127;
        int ch = cc & 7;
        uint32_t off = (uint32_t)kchunk * 16384 + r * 128 + ((uint32_t)(ch ^ (r & 7)) << 4);
        const size_t src = (size_t)(n0 + r) * KP + kchunk * 64 + ch * 8;
        cp_async16(sb + B_BASE + off, Bh + src);
        cp_async16(sb + B_BASE + TP * 16384 + off, Bl + src);
    }

    auto load_a = [&](int buf, int kchunk) {
        const uint32_t aB = sb + buf * A_STAGE;
#pragma unroll
        for (int i = 0; i < 4; ++i) {
            int cc = tid + i * 256;          // 0..1023
            int r  = cc >> 3;
            int ch = cc & 7;
            uint32_t off = r * 128 + ((uint32_t)(ch ^ (r & 7)) << 4);
            const size_t src = (size_t)(m0 + r) * KP + kchunk * 64 + ch * 8;
            cp_async16(aB + off, Ah + src);
            cp_async16(aB + 16384 + off, Al + src);
        }
    };

    load_a(0, 0);
    cp_commit();                         // group: B + A0

    float acc[2][8][4];
#pragma unroll
    for (int i = 0; i < 2; i++)
#pragma unroll
        for (int j = 0; j < 8; j++)
#pragma unroll
            for (int q = 0; q < 4; q++) acc[i][j][q] = 0.f;

    for (int c = 0; c < TP; ++c) {
        if (c + 1 < TP) { load_a((c + 1) & 1, c + 1); cp_commit(); cp_wait<1>(); }
        else            { cp_wait<0>(); }
        __syncthreads();

        const uint32_t ahB = sb + (c & 1) * A_STAGE;
        const uint32_t bhB = sb + B_BASE + c * 16384;
        const uint32_t blB = bhB + TP * 16384;
#pragma unroll
        for (int ks = 0; ks < 4; ++ks) {
            uint32_t a_h[2][4], a_l[2][4];
#pragma unroll
            for (int mi = 0; mi < 2; ++mi) {
                int row = wm * 32 + mi * 16 + (lane & 15);
                uint32_t chunk = (uint32_t)((ks << 1) + (lane >> 4));
                uint32_t addr = ahB + row * 128 + ((chunk ^ (row & 7)) << 4);
                ldsm_x4(a_h[mi], addr);
                ldsm_x4(a_l[mi], addr + 16384);
            }
            uint32_t b_h[8][2], b_l[8][2];
#pragma unroll
            for (int nj = 0; nj < 4; ++nj) {
                int g = lane >> 3;
                int nl = wn * 64 + nj * 16 + ((g >> 1) << 3) + (lane & 7);
                uint32_t chunk = (uint32_t)((ks << 1) + (g & 1));
                uint32_t swo = nl * 128 + ((chunk ^ (nl & 7)) << 4);
                uint32_t r4[4];
                ldsm_x4(r4, bhB + swo);
                b_h[nj * 2 + 0][0] = r4[0]; b_h[nj * 2 + 0][1] = r4[1];
                b_h[nj * 2 + 1][0] = r4[2]; b_h[nj * 2 + 1][1] = r4[3];
                ldsm_x4(r4, blB + swo);
                b_l[nj * 2 + 0][0] = r4[0]; b_l[nj * 2 + 0][1] = r4[1];
                b_l[nj * 2 + 1][0] = r4[2]; b_l[nj * 2 + 1][1] = r4[3];
            }
#pragma unroll
            for (int mi = 0; mi < 2; ++mi)
#pragma unroll
                for (int ni = 0; ni < 8; ++ni) {
                    mma_bf16(acc[mi][ni], a_h[mi], b_h[ni]);
                    mma_bf16(acc[mi][ni], a_h[mi], b_l[ni]);
                    mma_bf16(acc[mi][ni], a_l[mi], b_h[ni]);
                }
        }
        __syncthreads();
    }

    // epilogue: bias + relu, write fp32
    const int lr = lane >> 2;
    const int lc = (lane & 3) * 2;
#pragma unroll
    for (int mi = 0; mi < 2; ++mi) {
        int rb = m0 + wm * 32 + mi * 16 + lr;
#pragma unroll
        for (int half = 0; half < 2; ++half) {
            int r = rb + half * 8;
            if (r < N_NODES) {
                float* crow = C + (size_t)r * D_HID;
#pragma unroll
                for (int ni = 0; ni < 8; ++ni) {
                    int col = n0 + wn * 64 + ni * 8 + lc;
                    float2 bv = *reinterpret_cast<const float2*>(bias + col);
                    float2 o;
                    o.x = acc[mi][ni][half * 2 + 0] + bv.x;
                    o.y = acc[mi][ni][half * 2 + 1] + bv.y;
                    if (RELU) { o.x = fmaxf(o.x, 0.f); o.y = fmaxf(o.y, 0.f); }
                    *reinterpret_cast<float2*>(crow + col) = o;
                }
            }
        }
    }
}

// ---------------- launch ----------------------------------------------------
extern "C" void kernel_launch(void* const* d_in, const int* in_sizes, int n_in,
                              void* d_out, int out_size) {
    const float* x  = (const float*)d_in[0];
    const int*   ei = (const int*)  d_in[1];
    const float* W1 = (const float*)d_in[2];
    const float* b1 = (const float*)d_in[3];
    const float* W2 = (const float*)d_in[4];
    const float* b2 = (const float*)d_in[5];
    const float* W3 = (const float*)d_in[6];
    const float* b3 = (const float*)d_in[7];
    float* out = (float*)d_out;

    cudaFuncSetAttribute(k_gemm_mma<D_IN,  true >, cudaFuncAttributeMaxDynamicSharedMemorySize, SMEM_DYN_FOR(D_IN));
    cudaFuncSetAttribute(k_gemm_mma<D_HID, true >, cudaFuncAttributeMaxDynamicSharedMemorySize, SMEM_DYN_FOR(D_HID));
    cudaFuncSetAttribute(k_gemm_mma<D_HID, false>, cudaFuncAttributeMaxDynamicSharedMemorySize, SMEM_DYN_FOR(D_HID));

    void *p_h, *p_ah, *p_al, *p1h, *p1l, *p2h, *p2l, *p3h, *p3l;
    cudaGetSymbolAddress(&p_h,  g_h);
    cudaGetSymbolAddress(&p_ah, g_ah);
    cudaGetSymbolAddress(&p_al, g_al);
    cudaGetSymbolAddress(&p1h, g_w1h); cudaGetSymbolAddress(&p1l, g_w1l);
    cudaGetSymbolAddress(&p2h, g_w2h); cudaGetSymbolAddress(&p2l, g_w2l);
    cudaGetSymbolAddress(&p3h, g_w3h); cudaGetSymbolAddress(&p3l, g_w3l);
    float* h = (float*)p_h;
    __nv_bfloat16* ah = (__nv_bfloat16*)p_ah;
    __nv_bfloat16* al = (__nv_bfloat16*)p_al;

    // 1) fused degree count + weight split   2) scan (+deg reset)   3) fill
    k_count_split<<<(N_EDGES + SPLIT_ELEMS + 255) / 256, 256>>>(ei, W1, W2, W3);
    k_scan<<<1, 1024>>>();
    k_fill<<<(EN + 255) / 256, 256>>>(ei);

    const int aggBlocks = (N_NODES + 7) / 8;   // 8 warps/block, 1 warp/node
    dim3 gemmGrid(D_HID / BN, N_CTAS);

    // Layer 1: (A_hat x) W1 + b1, relu       (agg1 = 4th launch -> ncu capture)
    k_agg_split<D_IN><<<aggBlocks, 256>>>(x, ah, al);
    k_gemm_mma<D_IN, true><<<gemmGrid, 256, SMEM_DYN_FOR(D_IN)>>>(ah, al,
        (__nv_bfloat16*)p1h, (__nv_bfloat16*)p1l, b1, h);

    // Layer 2
    k_agg_split<D_HID><<<aggBlocks, 256>>>(h, ah, al);
    k_gemm_mma<D_HID, true><<<gemmGrid, 256, SMEM_DYN_FOR(D_HID)>>>(ah, al,
        (__nv_bfloat16*)p2h, (__nv_bfloat16*)p2l, b2, h);

    // Layer 3 (no relu), straight to output
    k_agg_split<D_HID><<<aggBlocks, 256>>>(h, ah, al);
    k_gemm_mma<D_HID, false><<<gemmGrid, 256, SMEM_DYN_FOR(D_HID)>>>(ah, al,
        (__nv_bfloat16*)p3h, (__nv_bfloat16*)p3l, b3, out);
}